// round 17
// baseline (speedup 1.0000x reference)
#include <cuda_runtime.h>
#include <cuda_fp16.h>
#include <cstdint>

// Problem constants
#define B_      4
#define C_IN_   32
#define C_OUT_  64
#define E_      200000
#define KK_     5
#define CKDIM   160
#define TILE_M  256
#define NTHR    512
#define NCH     20             // 16B chunks per A/B row (160 fp16 k-values)

#define TILES_PER_B  782       // 781 full + 1 tail (64 edges)
#define TOTAL_TILES  (B_ * TILES_PER_B)   // 3128
#define NCTA         148

// SMEM layout (1 CTA/SM)
#define SM_BH    0             // W fp16 panel: 64 x 320B = 20480
#define SM_A0    20480         // A panel buf0: 256 x 320B = 81920 (then acc stage)
#define SM_A1    102400        // A panel buf1
#define SM_CTRL  184320        // [0]=init tile, [1..2]=pnext, [3..4]=tile/sentinel
#define SM_TOTAL 184384

#define STG_PITCH 260          // floats per o-row in acc staging (bank-clean)

// Named barrier ids
#define BAR_READY0   1
#define BAR_READY1   2
#define BAR_OUT0     3
#define BAR_OUT1     4
#define BAR_PROD     5
#define BAR_CONS_INT 6
#define BAR_PROD_INT 7

// Global scratch
__device__ __align__(128) __half g_xh[(size_t)B_ * E_ * C_IN_];  // (B,E,C) fp16
__device__ int g_ctr;

// ---------------------------------------------------------------------------
// helpers
// ---------------------------------------------------------------------------
__device__ __forceinline__ uint32_t smem_u32(const void* p) {
    uint32_t a;
    asm("{ .reg .u64 t; cvta.to.shared.u64 t, %1; cvt.u32.u64 %0, t; }" : "=r"(a) : "l"(p));
    return a;
}
__device__ __forceinline__ int swzc(int kc, int row) {
    return (kc < 16) ? (kc ^ (row & 7)) : (16 + ((kc - 16) ^ (row & 3)));
}
__device__ __forceinline__ void ldm_x4(uint32_t* r, uint32_t addr) {
    asm volatile("ldmatrix.sync.aligned.m8n8.x4.shared.b16 {%0,%1,%2,%3}, [%4];"
        : "=r"(r[0]), "=r"(r[1]), "=r"(r[2]), "=r"(r[3]) : "r"(addr));
}
__device__ __forceinline__ void mma16816(float* d, const uint32_t* a, const uint32_t* b) {
    asm volatile(
        "mma.sync.aligned.m16n8k16.row.col.f32.f16.f16.f32 "
        "{%0,%1,%2,%3}, {%4,%5,%6,%7}, {%8,%9}, {%0,%1,%2,%3};"
        : "+f"(d[0]), "+f"(d[1]), "+f"(d[2]), "+f"(d[3])
        : "r"(a[0]), "r"(a[1]), "r"(a[2]), "r"(a[3]), "r"(b[0]), "r"(b[1]));
}
__device__ __forceinline__ void bar_sync(int id, int cnt) {
    asm volatile("bar.sync %0, %1;" :: "r"(id), "r"(cnt) : "memory");
}
__device__ __forceinline__ void bar_arrive(int id, int cnt) {
    asm volatile("bar.arrive %0, %1;" :: "r"(id), "r"(cnt) : "memory");
}

// ---------------------------------------------------------------------------
// Kernel 1: transpose x (B,C,E) fp32 -> g_xh (B,E,C) fp16. 64e x 32c tiles.
// ---------------------------------------------------------------------------
__global__ void __launch_bounds__(256) transpose_x(const float* __restrict__ x) {
    if (blockIdx.x == 0 && blockIdx.y == 0 && threadIdx.x == 0) g_ctr = 0;
    __shared__ float tile[32][65];
    const int b  = blockIdx.y;
    const int e0 = blockIdx.x * 64;
    const int t  = threadIdx.x;
    {
        const int c  = t >> 3;
        const int eo = (t & 7) * 8;
        const float4 v0 = *(const float4*)(x + ((size_t)b * C_IN_ + c) * E_ + e0 + eo);
        const float4 v1 = *(const float4*)(x + ((size_t)b * C_IN_ + c) * E_ + e0 + eo + 4);
        tile[c][eo + 0] = v0.x; tile[c][eo + 1] = v0.y;
        tile[c][eo + 2] = v0.z; tile[c][eo + 3] = v0.w;
        tile[c][eo + 4] = v1.x; tile[c][eo + 5] = v1.y;
        tile[c][eo + 6] = v1.z; tile[c][eo + 7] = v1.w;
    }
    __syncthreads();
    {
        const int e    = t >> 2;
        const int coct = t & 3;
        uint4 o;
        uint32_t* op = (uint32_t*)&o;
        #pragma unroll
        for (int p = 0; p < 4; p++) {
            const float a = tile[coct * 8 + p * 2][e];
            const float c = tile[coct * 8 + p * 2 + 1][e];
            __half2 h = __floats2half2_rn(a, c);
            op[p] = *reinterpret_cast<uint32_t*>(&h);
        }
        *(uint4*)(g_xh + ((size_t)b * E_ + e0 + e) * C_IN_ + coct * 8) = o;
    }
}

// ---------------------------------------------------------------------------
struct TileCtx { int b, e_base; };
__device__ __forceinline__ TileCtx decode_tile(int tile) {
    TileCtx tc;
    tc.b = tile / TILES_PER_B;
    tc.e_base = (tile - tc.b * TILES_PER_B) * TILE_M;
    return tc;
}

// ---------------------------------------------------------------------------
// Kernel 2: warp-specialized, 256-edge tiles, producer-side epilogue.
//   Consumers (t<256): HMMA, then stage accumulators into the dying A panel.
//   Producers (t>=256): gather/combine NEXT tile + coalesced STG of the tile
//   staged two visits ago (from the same panel, before refilling it).
// ---------------------------------------------------------------------------
__global__ void __launch_bounds__(NTHR, 1)
meshconv_kernel(const int*   __restrict__ Gi,
                const float* __restrict__ W,
                const float* __restrict__ bias,
                float*       __restrict__ out) {
    extern __shared__ __align__(1024) unsigned char smem[];
    const uint32_t sbase = smem_u32(smem);
    int* s_ctrl = (int*)(smem + SM_CTRL);

    const int t = threadIdx.x;

    // --- W fp16 panel built by all threads ----------------------------------
    #pragma unroll
    for (int r = 0; r < 20; r++) {
        const int i   = t + r * NTHR;
        const int o   = i / CKDIM;
        const int rem = i - o * CKDIM;
        const int c   = rem / KK_;
        const int j   = rem - c * KK_;
        const int k   = j * 32 + c;
        const uint32_t off = (uint32_t)((o * NCH + swzc(k >> 3, o)) * 16 + (k & 7) * 2);
        *reinterpret_cast<__half*>(smem + SM_BH + off) = __float2half_rn(W[i]);
    }
    if (t == 0) s_ctrl[0] = atomicAdd(&g_ctr, 1);
    __syncthreads();

    if (t >= 256) {
        // =================== PRODUCER (warps 8-15) ==========================
        const int pt    = t - 256;
        const int pw    = pt >> 5;
        const int pl    = pt & 31;
        const int e_sub = pt >> 2;     // combine: edge-within-64-slot
        const int quad  = pt & 3;      // combine: channel group
        float pbias[8];
        #pragma unroll
        for (int i = 0; i < 8; i++) pbias[i] = __ldg(&bias[pw * 8 + i]);

        // coalesced epilogue from staged acc in panel `aoff` for tile `tl`
        auto stg_flush = [&](int tl, uint32_t aoff) {
            const TileCtx tc = decode_tile(tl);
            const float* stg = (const float*)(smem + aoff);
            #pragma unroll
            for (int i = 0; i < 8; i++) {
                const int o = pw * 8 + i;
                const float pb = pbias[i];
                float* orow = out + ((size_t)(tc.b * C_OUT_ + o)) * E_ + tc.e_base;
                #pragma unroll
                for (int h = 0; h < 2; h++) {
                    const int e = h * 128 + pl * 4;
                    if (tc.e_base + e < E_) {
                        const float4 v = *(const float4*)(stg + o * STG_PITCH + e);
                        *(float4*)(orow + e) = make_float4(v.x + pb, v.y + pb,
                                                           v.z + pb, v.w + pb);
                    }
                }
            }
        };

        int tile = s_ctrl[0];
        int buf = 0, n = 0;
        int mp0 = -1, mp1 = -1;        // tile staged in each panel (awaiting STG)
        for (;;) {
            const uint32_t A = (buf == 0) ? SM_A0 : SM_A1;
            const bool haveTile = (tile < TOTAL_TILES);

            // register prefetch: Gi + first two gather slots (latency hides
            // under the flush stores below)
            int gidx[4][KK_];
            uint4 f[2][KK_];
            const __half* xb = 0;
            if (haveTile) {
                const TileCtx tc = decode_tile(tile);
                xb = g_xh + (size_t)tc.b * E_ * C_IN_;
                const int* GiB = Gi + ((size_t)tc.b * E_ + tc.e_base) * KK_;
                #pragma unroll
                for (int it = 0; it < 4; it++) {
                    const int e_loc = it * 64 + e_sub;
                    const bool ok = (tc.e_base + e_loc) < E_;
                    #pragma unroll
                    for (int j = 0; j < KK_; j++)
                        gidx[it][j] = ok ? GiB[e_loc * KK_ + j] : 0;
                }
                #pragma unroll
                for (int j = 0; j < KK_; j++)
                    f[0][j] = *(const uint4*)(xb + (size_t)gidx[0][j] * C_IN_ + quad * 8);
                #pragma unroll
                for (int j = 0; j < KK_; j++)
                    f[1][j] = *(const uint4*)(xb + (size_t)gidx[1][j] * C_IN_ + quad * 8);
            }

            // flush staged output occupying this panel (from two visits ago)
            if (n >= 2) {
                bar_sync((buf == 0) ? BAR_OUT0 : BAR_OUT1, NTHR);
                stg_flush((buf == 0) ? mp0 : mp1, A);
                bar_sync(BAR_PROD_INT, 256);       // flush reads done
            }

            if (!haveTile) {
                if (pt == 0) s_ctrl[3 + buf] = -1;
                bar_arrive((buf == 0) ? BAR_READY0 : BAR_READY1, NTHR);
                const int ob  = buf ^ 1;
                const int mpo = (ob == 0) ? mp0 : mp1;
                if (mpo >= 0) {
                    bar_sync((ob == 0) ? BAR_OUT0 : BAR_OUT1, NTHR);
                    stg_flush(mpo, (ob == 0) ? SM_A0 : SM_A1);
                }
                break;
            }

            // combine (2-deep pipelined gather) -> A panel
            #pragma unroll
            for (int it = 0; it < 4; it++) {
                uint4 fr[KK_];
                #pragma unroll
                for (int j = 0; j < KK_; j++) fr[j] = f[it & 1][j];
                if (it < 2) {
                    #pragma unroll
                    for (int j = 0; j < KK_; j++)
                        f[it & 1][j] = *(const uint4*)(xb + (size_t)gidx[it + 2][j] * C_IN_ + quad * 8);
                }
                const __half2* f1 = (const __half2*)&fr[1];
                const __half2* f2 = (const __half2*)&fr[2];
                const __half2* f3 = (const __half2*)&fr[3];
                const __half2* f4 = (const __half2*)&fr[4];
                uint4 gv[KK_];
                gv[0] = fr[0];
                __half2* g1 = (__half2*)&gv[1];
                __half2* g2 = (__half2*)&gv[2];
                __half2* g3 = (__half2*)&gv[3];
                __half2* g4 = (__half2*)&gv[4];
                #pragma unroll
                for (int p = 0; p < 4; p++) {
                    g1[p] = __hadd2(f1[p], f3[p]);
                    g2[p] = __hadd2(f2[p], f4[p]);
                    g3[p] = __habs2(__hsub2(f1[p], f3[p]));
                    g4[p] = __habs2(__hsub2(f2[p], f4[p]));
                }
                const int e_loc = it * 64 + e_sub;
                #pragma unroll
                for (int j = 0; j < KK_; j++) {
                    const int kc = j * 4 + quad;
                    const uint32_t off = (uint32_t)((e_loc * NCH + swzc(kc, e_loc)) * 16);
                    *(uint4*)(smem + A + off) = gv[j];
                }
            }
            if (pt == 0) {
                s_ctrl[1 + buf] = atomicAdd(&g_ctr, 1);
                s_ctrl[3 + buf] = tile;
            }
            bar_arrive((buf == 0) ? BAR_READY0 : BAR_READY1, NTHR);
            bar_sync(BAR_PROD, 256);               // pnext/tile visible
            if (buf == 0) mp0 = tile; else mp1 = tile;
            tile = s_ctrl[1 + buf];
            buf ^= 1;
            n++;
        }
    } else {
        // =================== CONSUMER (warps 0-7) ===========================
        const int cw = t >> 5;
        const int l  = t & 31;
        const int m0 = (cw & 3) * 32;       // within each 128-edge m-half
        const int n0 = (cw >> 2) * 32;
        const int mrA   = ((l >> 3) & 1) * 8 + (l & 7);
        const int kselA = (l >> 4);
        const int nrB   = ((l >> 4) & 1) * 8 + (l & 7);
        const int kselB = (l >> 3) & 1;

        int buf = 0;
        for (;;) {
            bar_sync((buf == 0) ? BAR_READY0 : BAR_READY1, NTHR);
            const int tile = s_ctrl[3 + buf];
            if (tile < 0) break;

            float acc[2][2][4][4];   // [m-half][16-row block][n-block][frag]
            #pragma unroll
            for (int a = 0; a < 2; a++)
                #pragma unroll
                for (int b2 = 0; b2 < 2; b2++)
                    #pragma unroll
                    for (int c2 = 0; c2 < 4; c2++)
                        #pragma unroll
                        for (int v = 0; v < 4; v++) acc[a][b2][c2][v] = 0.f;

            const uint32_t A = sbase + ((buf == 0) ? SM_A0 : SM_A1);
            #pragma unroll
            for (int ks = 0; ks < 10; ks++) {
                uint32_t b0[4], b1[4];
                {
                    const int kc = ks * 2 + kselB;
                    const int r0 = n0 + nrB;
                    const int r1 = r0 + 16;
                    ldm_x4(b0, sbase + SM_BH + (uint32_t)((r0 * NCH + swzc(kc, r0)) * 16));
                    ldm_x4(b1, sbase + SM_BH + (uint32_t)((r1 * NCH + swzc(kc, r1)) * 16));
                }
                #pragma unroll
                for (int mh = 0; mh < 2; mh++) {
                    uint32_t alo[4], ahi[4];
                    const int kc = ks * 2 + kselA;
                    const int rl = mh * 128 + m0 + mrA;
                    const int rh = rl + 16;
                    ldm_x4(alo, A + (uint32_t)((rl * NCH + swzc(kc, rl)) * 16));
                    ldm_x4(ahi, A + (uint32_t)((rh * NCH + swzc(kc, rh)) * 16));
                    mma16816(acc[mh][0][0], alo, b0);  mma16816(acc[mh][0][1], alo, b0 + 2);
                    mma16816(acc[mh][0][2], alo, b1);  mma16816(acc[mh][0][3], alo, b1 + 2);
                    mma16816(acc[mh][1][0], ahi, b0);  mma16816(acc[mh][1][1], ahi, b0 + 2);
                    mma16816(acc[mh][1][2], ahi, b1);  mma16816(acc[mh][1][3], ahi, b1 + 2);
                }
            }

            // all panel reads done across consumer warps, then stage acc
            bar_sync(BAR_CONS_INT, 256);
            {
                float* stg = (float*)(smem + ((buf == 0) ? SM_A0 : SM_A1));
                const int rb = m0 + (l >> 2);
                #pragma unroll
                for (int mh = 0; mh < 2; mh++) {
                    #pragma unroll
                    for (int mb = 0; mb < 2; mb++) {
                        const int e = mh * 128 + rb + mb * 16;
                        #pragma unroll
                        for (int nb = 0; nb < 4; nb++) {
                            const int nn = n0 + nb * 8 + (l & 3) * 2;
                            stg[nn * STG_PITCH + e]           = acc[mh][mb][nb][0];
                            stg[(nn + 1) * STG_PITCH + e]     = acc[mh][mb][nb][1];
                            stg[nn * STG_PITCH + e + 8]       = acc[mh][mb][nb][2];
                            stg[(nn + 1) * STG_PITCH + e + 8] = acc[mh][mb][nb][3];
                        }
                    }
                }
            }
            bar_arrive((buf == 0) ? BAR_OUT0 : BAR_OUT1, NTHR);
            buf ^= 1;
        }
    }
}

// ---------------------------------------------------------------------------
extern "C" void kernel_launch(void* const* d_in, const int* in_sizes, int n_in,
                              void* d_out, int out_size) {
    const float* x    = (const float*)d_in[0];
    const int*   Gi   = (const int*)  d_in[1];
    const float* W    = (const float*)d_in[2];
    const float* bias = (const float*)d_in[3];
    float*       out  = (float*)d_out;

    transpose_x<<<dim3(E_ / 64, B_), 256>>>(x);

    cudaFuncSetAttribute(meshconv_kernel,
                         cudaFuncAttributeMaxDynamicSharedMemorySize, SM_TOTAL);
    meshconv_kernel<<<NCTA, NTHR, SM_TOTAL>>>(Gi, W, bias, out);
}